// round 10
// baseline (speedup 1.0000x reference)
#include <cuda_runtime.h>

// Gegenbauer (alpha=0.5 -> Legendre) embedding: out[row, i-1] = C_i(x[row]), i=1..64.
// Round 10: persistent grid-stride kernel — grid sized to exactly one wave
// (occupancy API), each CTA loops over ~12 tiles. Eliminates ~11 wave
// transitions of the 15625-CTA launch. Body = best-measured R4/R9 variant:
// two 32-column passes, padded smem (PAD=9 f4, conflict-free STS/LDS),
// register-buffered compute, coalesced full-line copy-out.

#define DIM_OUT 64
#define RPB 128          // rows per tile == threads per block
#define HF4 8            // float4 per half-row (32 floats = 128B)
#define PAD 9            // smem row stride in float4

template <bool FULL>
__global__ void __launch_bounds__(RPB) geg_kernel(const float* __restrict__ x,
                                                  float* __restrict__ out,
                                                  int n, int ntiles) {
    __shared__ float4 s[RPB * PAD];   // 18,432 B

    const int tid = threadIdx.x;
    float4* __restrict__ o4 = reinterpret_cast<float4*>(out);
    const size_t total_f4 = ((size_t)n * DIM_OUT) / 4;

    for (int tile = blockIdx.x; tile < ntiles; tile += gridDim.x) {
        const size_t row = (size_t)tile * RPB + tid;
        const float xv = FULL ? x[row] : ((row < (size_t)n) ? x[row] : 0.0f);
        const size_t base_f4 = (size_t)tile * RPB * (DIM_OUT / 4);

        float c[32];
        float prev2 = 1.0f;   // C_0
        float prev  = xv;     // C_1 (alpha = 0.5)
        c[0] = xv;

        // ---- Pass 0: C_1..C_32 ----
        // C_i = ((2i-1)*x*C_{i-1} + (1-i)*C_{i-2}) * (1/i)
        #pragma unroll
        for (int i = 2; i <= 32; ++i) {
            const float A = (float)(2 * i - 1);
            const float B = (float)(1 - i);
            const float r = 1.0f / (float)i;
            const float ci = (A * xv * prev + B * prev2) * r;
            c[i - 1] = ci;
            prev2 = prev;
            prev  = ci;
        }

        #pragma unroll
        for (int j = 0; j < HF4; ++j)
            s[tid * PAD + j] = make_float4(c[4*j], c[4*j+1], c[4*j+2], c[4*j+3]);
        __syncthreads();

        #pragma unroll
        for (int j = 0; j < HF4; ++j) {
            const int f = j * RPB + tid;   // index within 128x8 f4 tile
            const int r = f >> 3;          // row within tile
            const int cq = f & 7;          // f4 column within half-row
            const size_t g = base_f4 + (size_t)r * (DIM_OUT / 4) + cq;
            if (FULL) {
                o4[g] = s[r * PAD + cq];
            } else if (g < total_f4) {
                o4[g] = s[r * PAD + cq];
            }
        }
        __syncthreads();

        // ---- Pass 1: C_33..C_64 (overlaps pass-0 stores in flight) ----
        #pragma unroll
        for (int i = 33; i <= DIM_OUT; ++i) {
            const float A = (float)(2 * i - 1);
            const float B = (float)(1 - i);
            const float r = 1.0f / (float)i;
            const float ci = (A * xv * prev + B * prev2) * r;
            c[i - 33] = ci;
            prev2 = prev;
            prev  = ci;
        }

        #pragma unroll
        for (int j = 0; j < HF4; ++j)
            s[tid * PAD + j] = make_float4(c[4*j], c[4*j+1], c[4*j+2], c[4*j+3]);
        __syncthreads();

        #pragma unroll
        for (int j = 0; j < HF4; ++j) {
            const int f = j * RPB + tid;
            const int r = f >> 3;
            const int cq = f & 7;
            const size_t g = base_f4 + (size_t)r * (DIM_OUT / 4) + HF4 + cq;
            if (FULL) {
                o4[g] = s[r * PAD + cq];
            } else if (g < total_f4) {
                o4[g] = s[r * PAD + cq];
            }
        }
        __syncthreads();   // guard smem reuse across loop iterations
    }
}

extern "C" void kernel_launch(void* const* d_in, const int* in_sizes, int n_in,
                              void* d_out, int out_size) {
    const float* x = (const float*)d_in[0];
    float* out = (float*)d_out;
    int n = in_sizes[0];   // 2,000,000 rows = 15625 full tiles of 128
    int ntiles = (n + RPB - 1) / RPB;
    const bool full = (n % RPB == 0);

    // One-wave grid: SM count x max resident CTAs for this kernel.
    int sms = 148, ctas_per_sm = 9;
    cudaDeviceGetAttribute(&sms, cudaDevAttrMultiProcessorCount, 0);
    if (full) {
        cudaOccupancyMaxActiveBlocksPerMultiprocessor(&ctas_per_sm,
                                                      geg_kernel<true>, RPB, 0);
    } else {
        cudaOccupancyMaxActiveBlocksPerMultiprocessor(&ctas_per_sm,
                                                      geg_kernel<false>, RPB, 0);
    }
    if (ctas_per_sm < 1) ctas_per_sm = 1;
    int grid = sms * ctas_per_sm;
    if (grid > ntiles) grid = ntiles;

    if (full) {
        geg_kernel<true><<<grid, RPB>>>(x, out, n, ntiles);
    } else {
        geg_kernel<false><<<grid, RPB>>>(x, out, n, ntiles);
    }
}

// round 11
// speedup vs baseline: 1.1300x; 1.1300x over previous
#include <cuda_runtime.h>

// Gegenbauer (alpha=0.5 -> Legendre) embedding: out[row, i-1] = C_i(x[row]), i=1..64.
// CONVERGED FINAL FORM — at the HBM3e write wall (~6.6 TB/s effective, DRAM ~75%).
// Evidence: 7 structural variants (occupancy 35-58%, STG.128/256, cache hints,
// TMA S2G, persistent grid) all pinned at 77-79 us ncu-time; best = this one.
//  - one thread per row, recurrence fully unrolled (constants fold to immediates)
//  - two 32-column passes through padded smem (PAD=9 f4: conflict-free STS & LDS)
//  - register-buffered compute, then tight STS burst
//  - unguarded full-tile copy-out (n = 128*15625 exactly), warps write full
//    128B lines; guarded fallback template for general n
//  - pass-1 compute overlaps pass-0 stores in flight; no trailing barrier

#define DIM_OUT 64
#define RPB 128          // rows per block == threads
#define HF4 8            // float4 per half-row (32 floats = 128B)
#define PAD 9            // smem row stride in float4

template <bool FULL>
__global__ void __launch_bounds__(RPB) geg_kernel(const float* __restrict__ x,
                                                  float* __restrict__ out,
                                                  int n) {
    __shared__ float4 s[RPB * PAD];   // 18,432 B

    const int tid = threadIdx.x;
    const size_t row = (size_t)blockIdx.x * RPB + tid;
    const float xv = FULL ? x[row] : ((row < (size_t)n) ? x[row] : 0.0f);

    float4* __restrict__ o4 = reinterpret_cast<float4*>(out);
    const size_t base_f4 = (size_t)blockIdx.x * RPB * (DIM_OUT / 4);
    const size_t total_f4 = ((size_t)n * DIM_OUT) / 4;

    float c[32];
    float prev2 = 1.0f;   // C_0
    float prev  = xv;     // C_1 (alpha = 0.5)
    c[0] = xv;

    // ---- Pass 0: compute C_1..C_32 into registers ----
    // C_i = ((2i-1)*x*C_{i-1} + (1-i)*C_{i-2}) * (1/i)
    #pragma unroll
    for (int i = 2; i <= 32; ++i) {
        const float A = (float)(2 * i - 1);
        const float B = (float)(1 - i);
        const float r = 1.0f / (float)i;
        const float ci = (A * xv * prev + B * prev2) * r;
        c[i - 1] = ci;
        prev2 = prev;
        prev  = ci;
    }

    #pragma unroll
    for (int j = 0; j < HF4; ++j)
        s[tid * PAD + j] = make_float4(c[4*j], c[4*j+1], c[4*j+2], c[4*j+3]);
    __syncthreads();

    // Coalesced copy-out of column block 0 (cols 0..31 of each row).
    #pragma unroll
    for (int j = 0; j < HF4; ++j) {
        const int f = j * RPB + tid;       // index within 128x8 f4 tile
        const int r = f >> 3;              // row within block
        const int cq = f & 7;              // f4 column within half-row
        const size_t g = base_f4 + (size_t)r * (DIM_OUT / 4) + cq;
        if (FULL) {
            o4[g] = s[r * PAD + cq];
        } else if (g < total_f4) {
            o4[g] = s[r * PAD + cq];
        }
    }
    __syncthreads();

    // ---- Pass 1: compute C_33..C_64 (overlaps pass-0 stores in flight) ----
    #pragma unroll
    for (int i = 33; i <= DIM_OUT; ++i) {
        const float A = (float)(2 * i - 1);
        const float B = (float)(1 - i);
        const float r = 1.0f / (float)i;
        const float ci = (A * xv * prev + B * prev2) * r;
        c[i - 33] = ci;
        prev2 = prev;
        prev  = ci;
    }

    #pragma unroll
    for (int j = 0; j < HF4; ++j)
        s[tid * PAD + j] = make_float4(c[4*j], c[4*j+1], c[4*j+2], c[4*j+3]);
    __syncthreads();

    // Coalesced copy-out of column block 1 (cols 32..63 of each row).
    #pragma unroll
    for (int j = 0; j < HF4; ++j) {
        const int f = j * RPB + tid;
        const int r = f >> 3;
        const int cq = f & 7;
        const size_t g = base_f4 + (size_t)r * (DIM_OUT / 4) + HF4 + cq;
        if (FULL) {
            o4[g] = s[r * PAD + cq];
        } else if (g < total_f4) {
            o4[g] = s[r * PAD + cq];
        }
    }
    // no trailing barrier: kernel exit synchronizes
}

extern "C" void kernel_launch(void* const* d_in, const int* in_sizes, int n_in,
                              void* d_out, int out_size) {
    const float* x = (const float*)d_in[0];
    float* out = (float*)d_out;
    int n = in_sizes[0];   // 2,000,000 rows = 15625 full tiles of 128
    int blocks = (n + RPB - 1) / RPB;
    if (n % RPB == 0) {
        geg_kernel<true><<<blocks, RPB>>>(x, out, n);
    } else {
        geg_kernel<false><<<blocks, RPB>>>(x, out, n);
    }
}